// round 7
// baseline (speedup 1.0000x reference)
#include <cuda_runtime.h>
#include <math.h>

// ESN: B=256, T=512, D=64, N=512, leak=0.5
// Output: [ X (B,T,N) fp32 ][ X_last (B,N) fp32 ]

#define BB 256
#define TT 512
#define DD 64
#define NN 512
#define LEAK 0.5f
#define NCTA 128
#define AS 516         // smem row stride (words): (4m+c) mod 32 all distinct
#define NGRP 8
#define GRP_SZ 16

typedef unsigned long long ull;

__device__ unsigned g_cnt[NGRP * 32];        // 128B-spaced group counters
__device__ float g_xt[2][BB][NN];            // tf32-prerounded x_t, double-buffered

__device__ __forceinline__ void fma2(ull &acc, ull a, ull b) {
    asm("fma.rn.f32x2 %0, %1, %2, %0;" : "+l"(acc) : "l"(a), "l"(b));
}
__device__ __forceinline__ float2 unpack2(ull v) {
    float2 r; asm("mov.b64 {%0, %1}, %2;" : "=f"(r.x), "=f"(r.y) : "l"(v)); return r;
}
__device__ __forceinline__ unsigned atom_add_rel(unsigned* p, unsigned v) {
    unsigned r;
    asm volatile("atom.add.release.gpu.global.u32 %0, [%1], %2;"
                 : "=r"(r) : "l"(p), "r"(v) : "memory");
    return r;
}
__device__ __forceinline__ unsigned ld_acq(const unsigned* p) {
    unsigned r;
    asm volatile("ld.acquire.gpu.global.u32 %0, [%1];" : "=r"(r) : "l"(p) : "memory");
    return r;
}
__device__ __forceinline__ float tf32r(float x) {
    unsigned u; asm("cvt.rna.tf32.f32 %0, %1;" : "=r"(u) : "f"(x));
    return __uint_as_float(u);
}
__device__ __forceinline__ void mma8(float &c0, float &c1, float &c2, float &c3,
                                     float a0, float a1, float a2, float a3,
                                     float b0, float b1) {
    asm("mma.sync.aligned.m16n8k8.row.col.f32.tf32.tf32.f32 "
        "{%0,%1,%2,%3},{%4,%5,%6,%7},{%8,%9},{%0,%1,%2,%3};"
        : "+f"(c0), "+f"(c1), "+f"(c2), "+f"(c3)
        : "r"(__float_as_uint(a0)), "r"(__float_as_uint(a1)),
          "r"(__float_as_uint(a2)), "r"(__float_as_uint(a3)),
          "r"(__float_as_uint(b0)), "r"(__float_as_uint(b1)));
}

// ---------------------------------------------------------------------------
// Projection: U = inputs@W_in + b_in; x0 = leak*tanh(U0) at t=0 (also stored
// tf32-rounded into g_xt[0]). Block (0,0) resets the group counters.
// ---------------------------------------------------------------------------
__global__ __launch_bounds__(128) void proj_kernel(
    const float* __restrict__ inp, const float* __restrict__ Win,
    const float* __restrict__ bin, float* __restrict__ X)
{
    __shared__ __align__(16) float Ash[DD][36];
    __shared__ __align__(16) float Wd[DD][64];

    const int tid = threadIdx.x;
    const int m0 = blockIdx.x * 32;
    const int n0 = blockIdx.y * 32;

    if (blockIdx.x == 0 && blockIdx.y == 0 && tid < NGRP)
        g_cnt[tid * 32] = 0u;

    {
        int c = tid & 63, mi = tid >> 6;
        #pragma unroll
        for (int j = 0; j < 16; j++) {
            int m = j * 2 + mi;
            Ash[c][m] = inp[(m0 + m) * DD + c];
        }
    }
    {
        int n = tid & 31, kw = tid >> 5;
        #pragma unroll
        for (int j = 0; j < 16; j++) {
            int k = j * 4 + kw;
            float w = Win[k * NN + n0 + n];
            Wd[k][2 * n] = w; Wd[k][2 * n + 1] = w;
        }
    }
    __syncthreads();

    const int tx = tid & 7;
    const int ty = tid >> 3;
    ull acc0 = 0, acc1 = 0, acc2 = 0, acc3 = 0;

    #pragma unroll
    for (int k = 0; k < DD; k++) {
        ull a = *(const ull*)&Ash[k][2 * ty];
        const ulonglong2* bp = (const ulonglong2*)&Wd[k][8 * tx];
        ulonglong2 b01 = bp[0], b23 = bp[1];
        fma2(acc0, a, b01.x); fma2(acc1, a, b01.y);
        fma2(acc2, a, b23.x); fma2(acc3, a, b23.y);
    }

    const int r0 = m0 + 2 * ty;
    const int t0 = r0 & (TT - 1);
    const int nb = n0 + 4 * tx;
    ull accs[4] = {acc0, acc1, acc2, acc3};
    #pragma unroll
    for (int c = 0; c < 4; c++) {
        float2 v = unpack2(accs[c]);
        int n = nb + c;
        float b = bin[n];
        float u0 = v.x + b;
        float u1 = v.y + b;
        if (t0 == 0) {
            float x0 = LEAK * tanhf(u0);
            X[(size_t)r0 * NN + n] = x0;
            g_xt[0][r0 >> 9][n] = tf32r(x0);
        } else {
            X[(size_t)r0 * NN + n] = u0;
        }
        X[(size_t)(r0 + 1) * NN + n] = u1;
    }
}

// ---------------------------------------------------------------------------
// Persistent tensor-core recurrence: 128 CTAs = 8 m-slabs x 16 n-tiles,
// 256 threads = 8 warps: quadrant q=warp&3 (2m x 2n of m16n16), k-half
// kh=warp>>2 (k in [kh*256, kh*256+256)). Partials combined via smem.
// A staged from g_xt (already tf32) -> pure copy. W hi/lo staged once.
// ---------------------------------------------------------------------------
__global__ __launch_bounds__(256, 1) void esn_mma(
    float* __restrict__ X, const float* __restrict__ Wres,
    const float* __restrict__ bres, float* __restrict__ xlast)
{
    extern __shared__ __align__(16) float smem[];
    float* Asm = smem;              // [32][AS]  tf32(x_prev), m x k
    float* Wh  = smem + 32 * AS;    // [32][AS]  tf32 hi, Wh[n][k]
    float* Wl  = Wh  + 32 * AS;     // [32][AS]  tf32 lo
    float* Rsm = Wl  + 32 * AS;     // [4][32][8] k-half partials

    const int tid  = threadIdx.x;
    const int warp = tid >> 5, lane = tid & 31;
    const int q    = warp & 3;      // quadrant
    const int kh   = warp >> 2;     // k-half
    const int bx   = blockIdx.x;
    const int grp  = bx & 7;
    const int m0   = grp * 32;
    const int n0   = (bx >> 3) * 32;
    const int TN   = TT * NN;
    unsigned* cnt  = &g_cnt[grp * 32];

    // ---- stage W hi/lo once ----
    {
        const int n = tid & 31;
        for (int k = tid >> 5; k < NN; k += 8) {
            float w  = Wres[k * NN + n0 + n];
            float hi = tf32r(w);
            Wh[n * AS + k] = hi;
            Wl[n * AS + k] = tf32r(w - hi);
        }
    }

    // fragment mapping
    const int wm  = q & 1, wn = q >> 1;
    const int gid = lane >> 2, tig = lane & 3;
    const int koff = kh * 256;
    const int r0  = m0 + 16 * wm + gid;          // rows r0, r0+8 (batch index)
    const int cb  = n0 + 16 * wn + 2 * tig;      // cols cb,cb+1; +8 for n8=1

    const float* arow0 = Asm + (16 * wm + gid) * AS + koff;
    const float* arow1 = arow0 + 8 * AS;
    const float* wh0 = Wh + (16 * wn + gid) * AS + koff;
    const float* wh1 = wh0 + 8 * AS;
    const float* wl0 = Wl + (16 * wn + gid) * AS + koff;
    const float* wl1 = wl0 + 8 * AS;
    float* rme = Rsm + (q * 32 + lane) * 8;

    // staging mapping: r = slab row 0..31, g = float4 phase 0..7
    const int sr = tid >> 3;
    const int sg = tid & 7;

    const float2 br0 = *(const float2*)&bres[cb];
    const float2 br1 = *(const float2*)&bres[cb + 8];

    // register-carried x_prev at output positions (kh==0 warps use them)
    float2 p00 = *(const float2*)&X[(size_t)r0 * TN + cb];
    float2 p01 = *(const float2*)&X[(size_t)r0 * TN + cb + 8];
    float2 p10 = *(const float2*)&X[(size_t)(r0 + 8) * TN + cb];
    float2 p11 = *(const float2*)&X[(size_t)(r0 + 8) * TN + cb + 8];

    for (int t = 1; t < TT; t++) {
        // ---- stage A slab: pure copy from pre-rounded g_xt ----
        {
            const float4* rp = (const float4*)&g_xt[(t - 1) & 1][m0 + sr][0];
            float* dr = Asm + sr * AS;
            #pragma unroll
            for (int j = 0; j < 16; j++) {
                int i4 = sg + 8 * j;
                float4 v = __ldcg(rp + i4);
                *(float4*)(dr + 4 * i4) = v;
            }
        }

        // ---- prefetch U (kh==0 warps only need it) ----
        size_t base = (size_t)r0 * TN + (size_t)t * NN + cb;
        float2 u00, u01, u10, u11;
        if (kh == 0) {
            u00 = __ldcg((const float2*)&X[base]);
            u01 = __ldcg((const float2*)&X[base + 8]);
            u10 = __ldcg((const float2*)&X[base + (size_t)8 * TN]);
            u11 = __ldcg((const float2*)&X[base + (size_t)8 * TN + 8]);
        }

        __syncthreads();

        // ---- tensor GEMM over this warp's k-half ----
        float h00 = 0.f, h01 = 0.f, h02 = 0.f, h03 = 0.f;
        float h10 = 0.f, h11 = 0.f, h12 = 0.f, h13 = 0.f;
        float l00 = 0.f, l01 = 0.f, l02 = 0.f, l03 = 0.f;
        float l10 = 0.f, l11 = 0.f, l12 = 0.f, l13 = 0.f;

        #pragma unroll 4
        for (int kb = 0; kb < 256; kb += 8) {
            float a0 = arow0[kb + tig];
            float a1 = arow1[kb + tig];
            float a2 = arow0[kb + tig + 4];
            float a3 = arow1[kb + tig + 4];
            mma8(h00, h01, h02, h03, a0, a1, a2, a3, wh0[kb + tig], wh0[kb + tig + 4]);
            mma8(h10, h11, h12, h13, a0, a1, a2, a3, wh1[kb + tig], wh1[kb + tig + 4]);
            mma8(l00, l01, l02, l03, a0, a1, a2, a3, wl0[kb + tig], wl0[kb + tig + 4]);
            mma8(l10, l11, l12, l13, a0, a1, a2, a3, wl1[kb + tig], wl1[kb + tig + 4]);
        }

        // ---- combine hi+lo; k-half reduction via smem ----
        float s0 = h00 + l00, s1 = h01 + l01, s2 = h02 + l02, s3 = h03 + l03;
        float s4 = h10 + l10, s5 = h11 + l11, s6 = h12 + l12, s7 = h13 + l13;
        if (kh == 1) {
            *(float4*)(rme + 0) = make_float4(s0, s1, s2, s3);
            *(float4*)(rme + 4) = make_float4(s4, s5, s6, s7);
        }
        __syncthreads();

        if (kh == 0) {
            float4 t0v = *(const float4*)(rme + 0);
            float4 t1v = *(const float4*)(rme + 4);
            s0 += t0v.x; s1 += t0v.y; s2 += t0v.z; s3 += t0v.w;
            s4 += t1v.x; s5 += t1v.y; s6 += t1v.z; s7 += t1v.w;

            // ---- epilogue: x_t = 0.5*x_prev + 0.5*tanh(U + s + b_res) ----
            float2 o00, o01, o10, o11;
            o00.x = 0.5f * p00.x + 0.5f * tanhf(u00.x + s0 + br0.x);
            o00.y = 0.5f * p00.y + 0.5f * tanhf(u00.y + s1 + br0.y);
            o10.x = 0.5f * p10.x + 0.5f * tanhf(u10.x + s2 + br0.x);
            o10.y = 0.5f * p10.y + 0.5f * tanhf(u10.y + s3 + br0.y);
            o01.x = 0.5f * p01.x + 0.5f * tanhf(u01.x + s4 + br1.x);
            o01.y = 0.5f * p01.y + 0.5f * tanhf(u01.y + s5 + br1.y);
            o11.x = 0.5f * p11.x + 0.5f * tanhf(u11.x + s6 + br1.x);
            o11.y = 0.5f * p11.y + 0.5f * tanhf(u11.y + s7 + br1.y);
            p00 = o00; p01 = o01; p10 = o10; p11 = o11;

            // fp32 outputs
            *(float2*)&X[base]                      = o00;
            *(float2*)&X[base + 8]                  = o01;
            *(float2*)&X[base + (size_t)8 * TN]     = o10;
            *(float2*)&X[base + (size_t)8 * TN + 8] = o11;
            if (t == TT - 1) {
                *(float2*)&xlast[(size_t)r0 * NN + cb]           = o00;
                *(float2*)&xlast[(size_t)r0 * NN + cb + 8]       = o01;
                *(float2*)&xlast[(size_t)(r0 + 8) * NN + cb]     = o10;
                *(float2*)&xlast[(size_t)(r0 + 8) * NN + cb + 8] = o11;
            }
            // tf32-prerounded copy for next step's staging
            float* xt = &g_xt[t & 1][r0][cb];
            float* xt8 = &g_xt[t & 1][r0 + 8][cb];
            xt[0]  = tf32r(o00.x); xt[1]  = tf32r(o00.y);
            xt[8]  = tf32r(o01.x); xt[9]  = tf32r(o01.y);
            xt8[0] = tf32r(o10.x); xt8[1] = tf32r(o10.y);
            xt8[8] = tf32r(o11.x); xt8[9] = tf32r(o11.y);
        }

        // ---- 16-CTA group barrier ----
        if (t < TT - 1) {
            __syncthreads();
            if (tid == 0) {
                atom_add_rel(cnt, 1u);
                unsigned target = (unsigned)t * GRP_SZ;
                while (ld_acq(cnt) < target) { }
            }
            __syncthreads();
        }
    }
}

extern "C" void kernel_launch(void* const* d_in, const int* in_sizes, int n_in,
                              void* d_out, int out_size)
{
    const float* inp  = (const float*)d_in[0];
    const float* Win  = (const float*)d_in[1];
    const float* bin  = (const float*)d_in[2];
    const float* Wres = (const float*)d_in[3];
    const float* bres = (const float*)d_in[4];

    float* X = (float*)d_out;                       // (B, T, N)
    float* xlast = X + (size_t)BB * TT * NN;        // (B, N)

    const int smem_bytes = (3 * 32 * AS + 4 * 32 * 8) * sizeof(float);  // 202240
    cudaFuncSetAttribute(esn_mma, cudaFuncAttributeMaxDynamicSharedMemorySize, smem_bytes);

    dim3 g1(BB * TT / 32, NN / 32);
    proj_kernel<<<g1, 128>>>(inp, Win, bin, X);

    esn_mma<<<NCTA, 256, smem_bytes>>>(X, Wres, bres, xlast);
}

// round 8
// speedup vs baseline: 1.1750x; 1.1750x over previous
#include <cuda_runtime.h>
#include <math.h>

// ESN: B=256, T=512, D=64, N=512, leak=0.5
// Output: [ X (B,T,N) fp32 ][ X_last (B,N) fp32 ]

#define BB 256
#define TT 512
#define DD 64
#define NN 512
#define LEAK 0.5f
#define NCTA 128
#define AS 516         // smem row stride (words): (4*gid+tig) mod 32 distinct
#define NGRP 8
#define GRP_SZ 16

typedef unsigned long long ull;

__device__ unsigned g_cnt[NGRP * 32];        // 128B-spaced group counters
__device__ float g_xt[2][BB][NN];            // tf32-prerounded x_t, double-buffered

__device__ __forceinline__ void fma2(ull &acc, ull a, ull b) {
    asm("fma.rn.f32x2 %0, %1, %2, %0;" : "+l"(acc) : "l"(a), "l"(b));
}
__device__ __forceinline__ float2 unpack2(ull v) {
    float2 r; asm("mov.b64 {%0, %1}, %2;" : "=f"(r.x), "=f"(r.y) : "l"(v)); return r;
}
__device__ __forceinline__ unsigned atom_add_rel(unsigned* p, unsigned v) {
    unsigned r;
    asm volatile("atom.add.release.gpu.global.u32 %0, [%1], %2;"
                 : "=r"(r) : "l"(p), "r"(v) : "memory");
    return r;
}
__device__ __forceinline__ unsigned ld_acq(const unsigned* p) {
    unsigned r;
    asm volatile("ld.acquire.gpu.global.u32 %0, [%1];" : "=r"(r) : "l"(p) : "memory");
    return r;
}
__device__ __forceinline__ float tf32r(float x) {
    unsigned u; asm("cvt.rna.tf32.f32 %0, %1;" : "=r"(u) : "f"(x));
    return __uint_as_float(u);
}
__device__ __forceinline__ void mma8(float &c0, float &c1, float &c2, float &c3,
                                     float a0, float a1, float a2, float a3,
                                     float b0, float b1) {
    asm("mma.sync.aligned.m16n8k8.row.col.f32.tf32.tf32.f32 "
        "{%0,%1,%2,%3},{%4,%5,%6,%7},{%8,%9},{%0,%1,%2,%3};"
        : "+f"(c0), "+f"(c1), "+f"(c2), "+f"(c3)
        : "r"(__float_as_uint(a0)), "r"(__float_as_uint(a1)),
          "r"(__float_as_uint(a2)), "r"(__float_as_uint(a3)),
          "r"(__float_as_uint(b0)), "r"(__float_as_uint(b1)));
}

// ---------------------------------------------------------------------------
// Projection: U = inputs@W_in + b_in; x0 = leak*tanh(U0) at t=0 (also stored
// tf32-rounded into g_xt[0]). Block (0,0) resets the group counters.
// ---------------------------------------------------------------------------
__global__ __launch_bounds__(128) void proj_kernel(
    const float* __restrict__ inp, const float* __restrict__ Win,
    const float* __restrict__ bin, float* __restrict__ X)
{
    __shared__ __align__(16) float Ash[DD][36];
    __shared__ __align__(16) float Wd[DD][64];

    const int tid = threadIdx.x;
    const int m0 = blockIdx.x * 32;
    const int n0 = blockIdx.y * 32;

    if (blockIdx.x == 0 && blockIdx.y == 0 && tid < NGRP)
        g_cnt[tid * 32] = 0u;

    {
        int c = tid & 63, mi = tid >> 6;
        #pragma unroll
        for (int j = 0; j < 16; j++) {
            int m = j * 2 + mi;
            Ash[c][m] = inp[(m0 + m) * DD + c];
        }
    }
    {
        int n = tid & 31, kw = tid >> 5;
        #pragma unroll
        for (int j = 0; j < 16; j++) {
            int k = j * 4 + kw;
            float w = Win[k * NN + n0 + n];
            Wd[k][2 * n] = w; Wd[k][2 * n + 1] = w;
        }
    }
    __syncthreads();

    const int tx = tid & 7;
    const int ty = tid >> 3;
    ull acc0 = 0, acc1 = 0, acc2 = 0, acc3 = 0;

    #pragma unroll
    for (int k = 0; k < DD; k++) {
        ull a = *(const ull*)&Ash[k][2 * ty];
        const ulonglong2* bp = (const ulonglong2*)&Wd[k][8 * tx];
        ulonglong2 b01 = bp[0], b23 = bp[1];
        fma2(acc0, a, b01.x); fma2(acc1, a, b01.y);
        fma2(acc2, a, b23.x); fma2(acc3, a, b23.y);
    }

    const int r0 = m0 + 2 * ty;
    const int t0 = r0 & (TT - 1);
    const int nb = n0 + 4 * tx;
    ull accs[4] = {acc0, acc1, acc2, acc3};
    #pragma unroll
    for (int c = 0; c < 4; c++) {
        float2 v = unpack2(accs[c]);
        int n = nb + c;
        float b = bin[n];
        float u0 = v.x + b;
        float u1 = v.y + b;
        if (t0 == 0) {
            float x0 = LEAK * tanhf(u0);
            X[(size_t)r0 * NN + n] = x0;
            g_xt[0][r0 >> 9][n] = tf32r(x0);
        } else {
            X[(size_t)r0 * NN + n] = u0;
        }
        X[(size_t)(r0 + 1) * NN + n] = u1;
    }
}

// ---------------------------------------------------------------------------
// Persistent tensor-core recurrence: 128 CTAs = 8 m-slabs x 16 n-tiles,
// 256 threads = 8 warps: quadrant q=warp&3 (2m x 2n of m16n16), k-half
// kh=warp>>2. Single tf32 pass (no W_lo). Release-early epilogue: g_xt
// stores -> release -> X STG + U prefetch overlap the poll.
// ---------------------------------------------------------------------------
__global__ __launch_bounds__(256, 1) void esn_mma(
    float* __restrict__ X, const float* __restrict__ Wres,
    const float* __restrict__ bres, float* __restrict__ xlast)
{
    extern __shared__ __align__(16) float smem[];
    float* Asm = smem;              // [32][AS]  tf32(x_prev), m x k
    float* Wh  = smem + 32 * AS;    // [32][AS]  tf32(W), Wh[n][k]
    float* Rsm = Wh  + 32 * AS;     // [4][32][8] k-half partials

    const int tid  = threadIdx.x;
    const int warp = tid >> 5, lane = tid & 31;
    const int q    = warp & 3;      // quadrant
    const int kh   = warp >> 2;     // k-half
    const int bx   = blockIdx.x;
    const int grp  = bx & 7;
    const int m0   = grp * 32;
    const int n0   = (bx >> 3) * 32;
    const int TN   = TT * NN;
    unsigned* cnt  = &g_cnt[grp * 32];

    // ---- stage W (single tf32) once ----
    {
        const int n = tid & 31;
        for (int k = tid >> 5; k < NN; k += 8)
            Wh[n * AS + k] = tf32r(Wres[k * NN + n0 + n]);
    }

    // fragment mapping
    const int wm  = q & 1, wn = q >> 1;
    const int gid = lane >> 2, tig = lane & 3;
    const int koff = kh * 256;
    const int r0  = m0 + 16 * wm + gid;          // rows r0, r0+8
    const int cb  = n0 + 16 * wn + 2 * tig;      // cols cb,cb+1; +8 for n8=1

    const float* arow0 = Asm + (16 * wm + gid) * AS + koff;
    const float* arow1 = arow0 + 8 * AS;
    const float* wh0 = Wh + (16 * wn + gid) * AS + koff;
    const float* wh1 = wh0 + 8 * AS;
    float* rme = Rsm + (q * 32 + lane) * 8;

    // staging mapping
    const int sr = tid >> 3;
    const int sg = tid & 7;

    const float2 br0 = *(const float2*)&bres[cb];
    const float2 br1 = *(const float2*)&bres[cb + 8];

    // register-carried x_prev (kh==0 warps)
    float2 p00 = *(const float2*)&X[(size_t)r0 * TN + cb];
    float2 p01 = *(const float2*)&X[(size_t)r0 * TN + cb + 8];
    float2 p10 = *(const float2*)&X[(size_t)(r0 + 8) * TN + cb];
    float2 p11 = *(const float2*)&X[(size_t)(r0 + 8) * TN + cb + 8];

    // U prefetch for t=1 (proj output; safe anytime)
    float2 u00, u01, u10, u11;
    {
        size_t b1 = (size_t)r0 * TN + (size_t)1 * NN + cb;
        if (kh == 0) {
            u00 = __ldcg((const float2*)&X[b1]);
            u01 = __ldcg((const float2*)&X[b1 + 8]);
            u10 = __ldcg((const float2*)&X[b1 + (size_t)8 * TN]);
            u11 = __ldcg((const float2*)&X[b1 + (size_t)8 * TN + 8]);
        }
    }

    for (int t = 1; t < TT; t++) {
        // ---- stage A slab: pure copy from pre-rounded g_xt ----
        {
            const float4* rp = (const float4*)&g_xt[(t - 1) & 1][m0 + sr][0];
            float* dr = Asm + sr * AS;
            #pragma unroll
            for (int j = 0; j < 16; j++) {
                int i4 = sg + 8 * j;
                float4 v = __ldcg(rp + i4);
                *(float4*)(dr + 4 * i4) = v;
            }
        }
        __syncthreads();

        // ---- tensor GEMM over this warp's k-half (single tf32 pass) ----
        float h00 = 0.f, h01 = 0.f, h02 = 0.f, h03 = 0.f;
        float h10 = 0.f, h11 = 0.f, h12 = 0.f, h13 = 0.f;

        #pragma unroll 8
        for (int kb = 0; kb < 256; kb += 8) {
            float a0 = arow0[kb + tig];
            float a1 = arow1[kb + tig];
            float a2 = arow0[kb + tig + 4];
            float a3 = arow1[kb + tig + 4];
            mma8(h00, h01, h02, h03, a0, a1, a2, a3, wh0[kb + tig], wh0[kb + tig + 4]);
            mma8(h10, h11, h12, h13, a0, a1, a2, a3, wh1[kb + tig], wh1[kb + tig + 4]);
        }

        // ---- k-half reduction via smem ----
        if (kh == 1) {
            *(float4*)(rme + 0) = make_float4(h00, h01, h02, h03);
            *(float4*)(rme + 4) = make_float4(h10, h11, h12, h13);
        }
        __syncthreads();

        size_t base = (size_t)r0 * TN + (size_t)t * NN + cb;
        float2 o00, o01, o10, o11;
        if (kh == 0) {
            float4 t0v = *(const float4*)(rme + 0);
            float4 t1v = *(const float4*)(rme + 4);
            float s0 = h00 + t0v.x, s1 = h01 + t0v.y;
            float s2 = h02 + t0v.z, s3 = h03 + t0v.w;
            float s4 = h10 + t1v.x, s5 = h11 + t1v.y;
            float s6 = h12 + t1v.z, s7 = h13 + t1v.w;

            o00.x = 0.5f * p00.x + 0.5f * tanhf(u00.x + s0 + br0.x);
            o00.y = 0.5f * p00.y + 0.5f * tanhf(u00.y + s1 + br0.y);
            o10.x = 0.5f * p10.x + 0.5f * tanhf(u10.x + s2 + br0.x);
            o10.y = 0.5f * p10.y + 0.5f * tanhf(u10.y + s3 + br0.y);
            o01.x = 0.5f * p01.x + 0.5f * tanhf(u01.x + s4 + br1.x);
            o01.y = 0.5f * p01.y + 0.5f * tanhf(u01.y + s5 + br1.y);
            o11.x = 0.5f * p11.x + 0.5f * tanhf(u11.x + s6 + br1.x);
            o11.y = 0.5f * p11.y + 0.5f * tanhf(u11.y + s7 + br1.y);
            p00 = o00; p01 = o01; p10 = o10; p11 = o11;

            // peers only need g_xt -> store it FIRST
            float* xt  = &g_xt[t & 1][r0][cb];
            float* xt8 = &g_xt[t & 1][r0 + 8][cb];
            xt[0]  = tf32r(o00.x); xt[1]  = tf32r(o00.y);
            xt[8]  = tf32r(o01.x); xt[9]  = tf32r(o01.y);
            xt8[0] = tf32r(o10.x); xt8[1] = tf32r(o10.y);
            xt8[8] = tf32r(o11.x); xt8[9] = tf32r(o11.y);
        }

        if (t < TT - 1) {
            __syncthreads();                 // all g_xt stores done CTA-wide
            if (tid == 0) atom_add_rel(cnt, 1u);   // release ASAP

            // ---- off-critical-path work overlaps the poll ----
            if (kh == 0) {
                *(float2*)&X[base]                      = o00;
                *(float2*)&X[base + 8]                  = o01;
                *(float2*)&X[base + (size_t)8 * TN]     = o10;
                *(float2*)&X[base + (size_t)8 * TN + 8] = o11;
                // U prefetch for step t+1
                size_t bn = base + NN;
                u00 = __ldcg((const float2*)&X[bn]);
                u01 = __ldcg((const float2*)&X[bn + 8]);
                u10 = __ldcg((const float2*)&X[bn + (size_t)8 * TN]);
                u11 = __ldcg((const float2*)&X[bn + (size_t)8 * TN + 8]);
            }
            if (tid == 0) {
                unsigned target = (unsigned)t * GRP_SZ;
                while (ld_acq(cnt) < target) { }
            }
            __syncthreads();
        } else if (kh == 0) {
            *(float2*)&X[base]                      = o00;
            *(float2*)&X[base + 8]                  = o01;
            *(float2*)&X[base + (size_t)8 * TN]     = o10;
            *(float2*)&X[base + (size_t)8 * TN + 8] = o11;
            *(float2*)&xlast[(size_t)r0 * NN + cb]           = o00;
            *(float2*)&xlast[(size_t)r0 * NN + cb + 8]       = o01;
            *(float2*)&xlast[(size_t)(r0 + 8) * NN + cb]     = o10;
            *(float2*)&xlast[(size_t)(r0 + 8) * NN + cb + 8] = o11;
        }
    }
}

extern "C" void kernel_launch(void* const* d_in, const int* in_sizes, int n_in,
                              void* d_out, int out_size)
{
    const float* inp  = (const float*)d_in[0];
    const float* Win  = (const float*)d_in[1];
    const float* bin  = (const float*)d_in[2];
    const float* Wres = (const float*)d_in[3];
    const float* bres = (const float*)d_in[4];

    float* X = (float*)d_out;                       // (B, T, N)
    float* xlast = X + (size_t)BB * TT * NN;        // (B, N)

    const int smem_bytes = (2 * 32 * AS + 4 * 32 * 8) * sizeof(float);  // 136192
    cudaFuncSetAttribute(esn_mma, cudaFuncAttributeMaxDynamicSharedMemorySize, smem_bytes);

    dim3 g1(BB * TT / 32, NN / 32);
    proj_kernel<<<g1, 128>>>(inp, Win, bin, X);

    esn_mma<<<NCTA, 256, smem_bytes>>>(X, Wres, bres, xlast);
}